// round 6
// baseline (speedup 1.0000x reference)
#include <cuda_runtime.h>
#include <math_constants.h>

#define H 1024
#define V 50257
#define L 12
#define TILES ((V + 7) / 8)          // 6283 blocks in k3, 8 rows each

// ---- device scratch (no allocations allowed), 16B-aligned ----
__device__ __align__(16) float g_xin[2 * H];   // [embedded ; attn_applied]
__device__ __align__(16) float g_x[H];         // relu(combine) output
__device__ __align__(16) float g_h[H];         // h_new (aligned copy)
__device__ __align__(16) float g_hh[4 * H];    // W_hh@h0 + b_ih + b_hh
__device__ __align__(16) float g_ps[TILES];    // per-block sum(exp(logit))
__device__ float g_lse;                        // final log-sum-exp
__device__ unsigned g_tick = 0;                // k3 completion ticket

__device__ __forceinline__ float warp_sum(float v) {
#pragma unroll
    for (int o = 16; o; o >>= 1) v += __shfl_xor_sync(0xffffffffu, v, o);
    return v;
}

__device__ __forceinline__ float4 ldcs4(const float4* p) { return __ldcs(p); }

// ============================================================
// Kernel 0: embedding + attention softmax + applied context.
// Single block, 384 threads. Writes g_xin = [emb ; applied], attnw.
// ============================================================
__global__ void k0_attn(const int* input,
                        const float* __restrict__ h_hidden,
                        const float* __restrict__ enc,
                        const float* __restrict__ emb,
                        const float* __restrict__ attn_W,
                        const float* __restrict__ attn_b,
                        float* __restrict__ attnw_out) {
    __shared__ __align__(16) float s_in[2 * H];
    __shared__ float s_logit[L];
    __shared__ float s_w[L];
    const int tid = threadIdx.x;

    const int idx = input[0];      // low 32 bits of LE int64 index
    const float* e = emb + (size_t)idx * H;
    for (int i = tid; i < H; i += 384) {
        float v = e[i];
        s_in[i] = v;
        g_xin[i] = v;
        s_in[H + i] = h_hidden[i];
    }
    __syncthreads();

    const int w = tid >> 5, lane = tid & 31;
    if (w < L) {
        const float4* row = (const float4*)(attn_W + (size_t)w * 2 * H);
        const float4* s4 = (const float4*)s_in;
        float acc = 0.f;
#pragma unroll
        for (int t = 0; t < 16; t++) {
            float4 a = row[lane + 32 * t];
            float4 b = s4[lane + 32 * t];
            acc += a.x * b.x + a.y * b.y + a.z * b.z + a.w * b.w;
        }
        acc = warp_sum(acc);
        if (lane == 0) s_logit[w] = acc + attn_b[w];
    }
    __syncthreads();

    if (tid == 0) {
        float m = -1e30f;
#pragma unroll
        for (int l = 0; l < L; l++) m = fmaxf(m, s_logit[l]);
        float s = 0.f;
#pragma unroll
        for (int l = 0; l < L; l++) { float ex = expf(s_logit[l] - m); s_w[l] = ex; s += ex; }
        float inv = 1.f / s;
#pragma unroll
        for (int l = 0; l < L; l++) { s_w[l] *= inv; attnw_out[l] = s_w[l]; }
    }
    __syncthreads();

    for (int j = tid; j < H; j += 384) {
        float acc = 0.f;
#pragma unroll
        for (int l = 0; l < L; l++) acc += s_w[l] * enc[l * H + j];
        g_xin[H + j] = acc;
    }
}

// ============================================================
// Kernel 1: uniform matvec streamer, 640 blocks x 256 threads.
//   blocks 0..127   : combine rows (8/block):  g_x = relu(comb_W@xin + b)
//   blocks 128..639 : hh gate rows (8/block):  g_hh = W_hh@h0 + b_ih + b_hh
// Both paths are simple 1-row-per-warp dots: low regs, high occupancy.
// ============================================================
__global__ void __launch_bounds__(256, 6)
k1_comb_hh(const float* __restrict__ h_hidden,
           const float* __restrict__ comb_W,
           const float* __restrict__ comb_b,
           const float* __restrict__ W_hh,
           const float* __restrict__ b_ih,
           const float* __restrict__ b_hh) {
    __shared__ __align__(16) float4 s_v[512];    // 2048 floats max
    const int tid = threadIdx.x;
    const int w = tid >> 5, lane = tid & 31;

    if (blockIdx.x < 128) {
        // combine: vector = g_xin (2H)
        const float4* x4 = (const float4*)g_xin;
        s_v[tid] = x4[tid];
        s_v[tid + 256] = x4[tid + 256];
        __syncthreads();
        const int r = blockIdx.x * 8 + w;
        const float4* row = (const float4*)(comb_W + (size_t)r * 2 * H);
        float acc = 0.f;
#pragma unroll
        for (int t = 0; t < 16; t++) {
            float4 a = ldcs4(row + lane + 32 * t);
            float4 b = s_v[lane + 32 * t];
            acc += a.x * b.x + a.y * b.y + a.z * b.z + a.w * b.w;
        }
        acc = warp_sum(acc);
        if (lane == 0) g_x[r] = fmaxf(acc + comb_b[r], 0.f);
    } else {
        // hh gates: vector = h0 (H)
        const float4* h4 = (const float4*)h_hidden;
        s_v[tid] = h4[tid];
        __syncthreads();
        const int r = (blockIdx.x - 128) * 8 + w;    // [0, 4096)
        const float4* row = (const float4*)(W_hh + (size_t)r * H);
        float acc = 0.f;
#pragma unroll
        for (int t = 0; t < 8; t++) {
            float4 a = ldcs4(row + lane + 32 * t);
            float4 b = s_v[lane + 32 * t];
            acc += a.x * b.x + a.y * b.y + a.z * b.z + a.w * b.w;
        }
        acc = warp_sum(acc);
        if (lane == 0) g_hh[r] = acc + b_ih[r] + b_hh[r];
    }
}

// ============================================================
// Kernel 2: ih-half of gates + LSTM cell, fused.
// One warp per hidden unit j (4 W_ih rows, processed pairwise).
// ============================================================
__global__ void k2_gates_cell(const float* __restrict__ c_hidden,
                              const float* __restrict__ W_ih,
                              float* __restrict__ h_new,
                              float* __restrict__ c_new) {
    __shared__ __align__(16) float4 s_x[256];
    const int tid = threadIdx.x;
    s_x[tid] = ((const float4*)g_x)[tid];
    __syncthreads();

    const int w = tid >> 5, lane = tid & 31;
    const int j = blockIdx.x * 8 + w;

    float gate[4];
#pragma unroll
    for (int gp = 0; gp < 2; gp++) {
        const float4* r0 = (const float4*)(W_ih + (size_t)((2 * gp) * H + j) * H);
        const float4* r1 = (const float4*)(W_ih + (size_t)((2 * gp + 1) * H + j) * H);
        float a0 = 0.f, a1 = 0.f;
#pragma unroll
        for (int t = 0; t < 8; t++) {
            float4 w0 = ldcs4(r0 + lane + 32 * t);
            float4 w1 = ldcs4(r1 + lane + 32 * t);
            float4 xb = s_x[lane + 32 * t];
            a0 += w0.x * xb.x + w0.y * xb.y + w0.z * xb.z + w0.w * xb.w;
            a1 += w1.x * xb.x + w1.y * xb.y + w1.z * xb.z + w1.w * xb.w;
        }
        gate[2 * gp]     = warp_sum(a0);
        gate[2 * gp + 1] = warp_sum(a1);
    }
    if (lane == 0) {
        float gi = gate[0] + g_hh[j];
        float gf = gate[1] + g_hh[H + j];
        float gg = gate[2] + g_hh[2 * H + j];
        float go = gate[3] + g_hh[3 * H + j];
        float si = 1.f / (1.f + expf(-gi));
        float sf = 1.f / (1.f + expf(-gf));
        float so = 1.f / (1.f + expf(-go));
        float c = sf * c_hidden[j] + si * tanhf(gg);
        float h = so * tanhf(c);
        c_new[j] = c;
        h_new[j] = h;
        g_h[j] = h;
    }
}

// ============================================================
// Kernel 3: output projection (50257 x 1024), 8 rows/block,
// one warp per row; per-block sum(exp) partial. The LAST block
// to finish reduces all partials in fixed index order -> g_lse.
// Logits are bounded (|l| <~ 32) so plain exp is safe.
// ============================================================
__global__ void k3_out(const float* __restrict__ out_W,
                       const float* __restrict__ out_b,
                       float* __restrict__ logits) {
    __shared__ __align__(16) float4 s_h[256];
    __shared__ float s_l[8];
    __shared__ float s_part[8];
    __shared__ int s_last;
    const int tid = threadIdx.x;
    s_h[tid] = ((const float4*)g_h)[tid];
    __syncthreads();

    const int w = tid >> 5, lane = tid & 31;
    const int r = blockIdx.x * 8 + w;
    float l = -CUDART_INF_F;
    if (r < V) {
        const float4* row = (const float4*)(out_W + (size_t)r * H);
        float acc = 0.f;
#pragma unroll
        for (int t = 0; t < 8; t++) {
            float4 a = ldcs4(row + lane + 32 * t);
            float4 b = s_h[lane + 32 * t];
            acc += a.x * b.x + a.y * b.y + a.z * b.z + a.w * b.w;
        }
        acc = warp_sum(acc);
        if (lane == 0) {
            l = acc + out_b[r];
            logits[r] = l;
        }
    }
    if (lane == 0) s_l[w] = l;
    __syncthreads();
    if (tid == 0) {
        float s = 0.f;
#pragma unroll
        for (int i = 0; i < 8; i++) {
            float v = s_l[i];
            if (v != -CUDART_INF_F) s += expf(v);
        }
        g_ps[blockIdx.x] = s;
        __threadfence();                              // publish partial
        unsigned prev = atomicAdd(&g_tick, 1u);
        s_last = (prev == TILES - 1);
    }
    __syncthreads();

    if (s_last) {
        __threadfence();                              // acquire all partials
        float s = 0.f;
        for (int i = tid; i < TILES; i += 256) s += __ldcg(&g_ps[i]);
        s = warp_sum(s);
        if (lane == 0) s_part[w] = s;
        __syncthreads();
        if (tid == 0) {
            float tot = 0.f;
#pragma unroll
            for (int i = 0; i < 8; i++) tot += s_part[i];
            g_lse = logf(tot);
            g_tick = 0;                               // reset for graph replay
        }
    }
}

// ============================================================
// Kernel 4: logp[i] = logits[i] - g_lse (L2-resident elementwise)
// ============================================================
__global__ void k4_sub(float* __restrict__ logp) {
    const int i = blockIdx.x * 256 + threadIdx.x;
    if (i < V) logp[i] -= g_lse;
}

// ============================================================
extern "C" void kernel_launch(void* const* d_in, const int* in_sizes, int n_in,
                              void* d_out, int out_size) {
    const int*   input   = (const int*)  d_in[0];
    const float* h_hid   = (const float*)d_in[1];
    const float* c_hid   = (const float*)d_in[2];
    const float* enc     = (const float*)d_in[3];
    const float* emb     = (const float*)d_in[4];
    const float* attn_W  = (const float*)d_in[5];
    const float* attn_b  = (const float*)d_in[6];
    const float* comb_W  = (const float*)d_in[7];
    const float* comb_b  = (const float*)d_in[8];
    const float* W_ih    = (const float*)d_in[9];
    const float* W_hh    = (const float*)d_in[10];
    const float* b_ih    = (const float*)d_in[11];
    const float* b_hh    = (const float*)d_in[12];
    const float* out_W   = (const float*)d_in[13];
    const float* out_b   = (const float*)d_in[14];

    float* out   = (float*)d_out;
    float* logp  = out;                 // [V]
    float* h_new = out + V;             // [H]
    float* c_new = out + V + H;         // [H]
    float* attnw = out + V + 2 * H;     // [L]

    k0_attn<<<1, 384>>>(input, h_hid, enc, emb, attn_W, attn_b, attnw);
    k1_comb_hh<<<640, 256>>>(h_hid, comb_W, comb_b, W_hh, b_ih, b_hh);
    k2_gates_cell<<<128, 256>>>(c_hid, W_ih, h_new, c_new);
    k3_out<<<TILES, 256>>>(out_W, out_b, logp);
    k4_sub<<<(V + 255) / 256, 256>>>(logp);
}

// round 7
// speedup vs baseline: 1.1093x; 1.1093x over previous
#include <cuda_runtime.h>
#include <math_constants.h>

#define H 1024
#define V 50257
#define L 12
#define TILES ((V + 7) / 8)          // 6283 blocks in k3, 8 rows each

// ---- device scratch (no allocations allowed), 16B-aligned ----
__device__ __align__(16) float g_xin[2 * H];   // [embedded ; attn_applied]
__device__ __align__(16) float g_x[H];         // relu(combine) output
__device__ __align__(16) float g_h[H];         // h_new (aligned copy)
__device__ __align__(16) float g_hh[4 * H];    // W_hh@h0 + b_ih + b_hh
__device__ __align__(16) float g_ps[TILES];    // per-block sum(exp(logit))
__device__ float g_lse;                        // final log-sum-exp

__device__ __forceinline__ float warp_sum(float v) {
#pragma unroll
    for (int o = 16; o; o >>= 1) v += __shfl_xor_sync(0xffffffffu, v, o);
    return v;
}

__device__ __forceinline__ float4 ldcs4(const float4* p) { return __ldcs(p); }

// ============================================================
// Kernel 0: embedding + attention softmax + applied context.
// Single block, 384 threads. Writes g_xin = [emb ; applied], attnw.
// ============================================================
__global__ void k0_attn(const int* input,
                        const float* __restrict__ h_hidden,
                        const float* __restrict__ enc,
                        const float* __restrict__ emb,
                        const float* __restrict__ attn_W,
                        const float* __restrict__ attn_b,
                        float* __restrict__ attnw_out) {
    __shared__ __align__(16) float s_in[2 * H];
    __shared__ float s_logit[L];
    __shared__ float s_w[L];
    const int tid = threadIdx.x;

    const int idx = input[0];      // low 32 bits of LE int64 index
    const float* e = emb + (size_t)idx * H;
    for (int i = tid; i < H; i += 384) {
        float v = e[i];
        s_in[i] = v;
        g_xin[i] = v;
        s_in[H + i] = h_hidden[i];
    }
    __syncthreads();

    const int w = tid >> 5, lane = tid & 31;
    if (w < L) {
        const float4* row = (const float4*)(attn_W + (size_t)w * 2 * H);
        const float4* s4 = (const float4*)s_in;
        float acc = 0.f;
#pragma unroll
        for (int t = 0; t < 16; t++) {
            float4 a = row[lane + 32 * t];
            float4 b = s4[lane + 32 * t];
            acc += a.x * b.x + a.y * b.y + a.z * b.z + a.w * b.w;
        }
        acc = warp_sum(acc);
        if (lane == 0) s_logit[w] = acc + attn_b[w];
    }
    __syncthreads();

    if (tid == 0) {
        float m = -1e30f;
#pragma unroll
        for (int l = 0; l < L; l++) m = fmaxf(m, s_logit[l]);
        float s = 0.f;
#pragma unroll
        for (int l = 0; l < L; l++) { float ex = expf(s_logit[l] - m); s_w[l] = ex; s += ex; }
        float inv = 1.f / s;
#pragma unroll
        for (int l = 0; l < L; l++) { s_w[l] *= inv; attnw_out[l] = s_w[l]; }
    }
    __syncthreads();

    for (int j = tid; j < H; j += 384) {
        float acc = 0.f;
#pragma unroll
        for (int l = 0; l < L; l++) acc += s_w[l] * enc[l * H + j];
        g_xin[H + j] = acc;
    }
}

// ============================================================
// Kernel 1: uniform matvec streamer, 640 blocks x 256 threads.
//   blocks 0..127   : combine rows (8/block):  g_x = relu(comb_W@xin + b)
//   blocks 128..639 : hh gate rows (8/block):  g_hh = W_hh@h0 + b_ih + b_hh
// ============================================================
__global__ void __launch_bounds__(256, 6)
k1_comb_hh(const float* __restrict__ h_hidden,
           const float* __restrict__ comb_W,
           const float* __restrict__ comb_b,
           const float* __restrict__ W_hh,
           const float* __restrict__ b_ih,
           const float* __restrict__ b_hh) {
    __shared__ __align__(16) float4 s_v[512];    // 2048 floats max
    const int tid = threadIdx.x;
    const int w = tid >> 5, lane = tid & 31;

    if (blockIdx.x < 128) {
        const float4* x4 = (const float4*)g_xin;
        s_v[tid] = x4[tid];
        s_v[tid + 256] = x4[tid + 256];
        __syncthreads();
        const int r = blockIdx.x * 8 + w;
        const float4* row = (const float4*)(comb_W + (size_t)r * 2 * H);
        float acc = 0.f;
#pragma unroll
        for (int t = 0; t < 16; t++) {
            float4 a = ldcs4(row + lane + 32 * t);
            float4 b = s_v[lane + 32 * t];
            acc += a.x * b.x + a.y * b.y + a.z * b.z + a.w * b.w;
        }
        acc = warp_sum(acc);
        if (lane == 0) g_x[r] = fmaxf(acc + comb_b[r], 0.f);
    } else {
        const float4* h4 = (const float4*)h_hidden;
        s_v[tid] = h4[tid];
        __syncthreads();
        const int r = (blockIdx.x - 128) * 8 + w;    // [0, 4096)
        const float4* row = (const float4*)(W_hh + (size_t)r * H);
        float acc = 0.f;
#pragma unroll
        for (int t = 0; t < 8; t++) {
            float4 a = ldcs4(row + lane + 32 * t);
            float4 b = s_v[lane + 32 * t];
            acc += a.x * b.x + a.y * b.y + a.z * b.z + a.w * b.w;
        }
        acc = warp_sum(acc);
        if (lane == 0) g_hh[r] = acc + b_ih[r] + b_hh[r];
    }
}

// ============================================================
// Kernel 2: ih-half of gates + LSTM cell, fused.
// One warp per hidden unit j (4 W_ih rows, processed pairwise).
// ============================================================
__global__ void k2_gates_cell(const float* __restrict__ c_hidden,
                              const float* __restrict__ W_ih,
                              float* __restrict__ h_new,
                              float* __restrict__ c_new) {
    __shared__ __align__(16) float4 s_x[256];
    const int tid = threadIdx.x;
    s_x[tid] = ((const float4*)g_x)[tid];
    __syncthreads();

    const int w = tid >> 5, lane = tid & 31;
    const int j = blockIdx.x * 8 + w;

    float gate[4];
#pragma unroll
    for (int gp = 0; gp < 2; gp++) {
        const float4* r0 = (const float4*)(W_ih + (size_t)((2 * gp) * H + j) * H);
        const float4* r1 = (const float4*)(W_ih + (size_t)((2 * gp + 1) * H + j) * H);
        float a0 = 0.f, a1 = 0.f;
#pragma unroll
        for (int t = 0; t < 8; t++) {
            float4 w0 = ldcs4(r0 + lane + 32 * t);
            float4 w1 = ldcs4(r1 + lane + 32 * t);
            float4 xb = s_x[lane + 32 * t];
            a0 += w0.x * xb.x + w0.y * xb.y + w0.z * xb.z + w0.w * xb.w;
            a1 += w1.x * xb.x + w1.y * xb.y + w1.z * xb.z + w1.w * xb.w;
        }
        gate[2 * gp]     = warp_sum(a0);
        gate[2 * gp + 1] = warp_sum(a1);
    }
    if (lane == 0) {
        float gi = gate[0] + g_hh[j];
        float gf = gate[1] + g_hh[H + j];
        float gg = gate[2] + g_hh[2 * H + j];
        float go = gate[3] + g_hh[3 * H + j];
        float si = 1.f / (1.f + expf(-gi));
        float sf = 1.f / (1.f + expf(-gf));
        float so = 1.f / (1.f + expf(-go));
        float c = sf * c_hidden[j] + si * tanhf(gg);
        float h = so * tanhf(c);
        c_new[j] = c;
        h_new[j] = h;
        g_h[j] = h;
    }
}

// ============================================================
// Kernel 3: output projection (50257 x 1024), 8 rows/block,
// one warp per row; emits per-block sum(exp(logit)) partial.
// NO fences/atomics in the epilogue — blocks retire immediately.
// Logits are bounded (|l| <~ 32) so plain exp is safe.
// ============================================================
__global__ void k3_out(const float* __restrict__ out_W,
                       const float* __restrict__ out_b,
                       float* __restrict__ logits) {
    __shared__ __align__(16) float4 s_h[256];
    __shared__ float s_l[8];
    const int tid = threadIdx.x;
    s_h[tid] = ((const float4*)g_h)[tid];
    __syncthreads();

    const int w = tid >> 5, lane = tid & 31;
    const int r = blockIdx.x * 8 + w;
    float l = -CUDART_INF_F;
    if (r < V) {
        const float4* row = (const float4*)(out_W + (size_t)r * H);
        float acc = 0.f;
#pragma unroll
        for (int t = 0; t < 8; t++) {
            float4 a = ldcs4(row + lane + 32 * t);
            float4 b = s_h[lane + 32 * t];
            acc += a.x * b.x + a.y * b.y + a.z * b.z + a.w * b.w;
        }
        acc = warp_sum(acc);
        if (lane == 0) {
            l = acc + out_b[r];
            logits[r] = l;
        }
    }
    if (lane == 0) s_l[w] = l;
    __syncthreads();
    if (tid == 0) {
        float s = 0.f;
#pragma unroll
        for (int i = 0; i < 8; i++) {
            float v = s_l[i];
            if (v != -CUDART_INF_F) s += expf(v);
        }
        g_ps[blockIdx.x] = s;
    }
}

// ============================================================
// Kernel 3.5: reduce 6283 L2-resident partials -> g_lse.
// Single block, 256 threads, deterministic order.
// ============================================================
__global__ void k_lse() {
    __shared__ float s_part[8];
    const int tid = threadIdx.x;
    const int w = tid >> 5, lane = tid & 31;
    float s = 0.f;
    for (int i = tid; i < TILES; i += 256) s += g_ps[i];
    s = warp_sum(s);
    if (lane == 0) s_part[w] = s;
    __syncthreads();
    if (tid == 0) {
        float tot = 0.f;
#pragma unroll
        for (int i = 0; i < 8; i++) tot += s_part[i];
        g_lse = logf(tot);
    }
}

// ============================================================
// Kernel 4: logp[i] = logits[i] - g_lse (L2-resident elementwise)
// ============================================================
__global__ void k4_sub(float* __restrict__ logp) {
    const int i = blockIdx.x * 256 + threadIdx.x;
    if (i < V) logp[i] -= g_lse;
}

// ============================================================
extern "C" void kernel_launch(void* const* d_in, const int* in_sizes, int n_in,
                              void* d_out, int out_size) {
    const int*   input   = (const int*)  d_in[0];
    const float* h_hid   = (const float*)d_in[1];
    const float* c_hid   = (const float*)d_in[2];
    const float* enc     = (const float*)d_in[3];
    const float* emb     = (const float*)d_in[4];
    const float* attn_W  = (const float*)d_in[5];
    const float* attn_b  = (const float*)d_in[6];
    const float* comb_W  = (const float*)d_in[7];
    const float* comb_b  = (const float*)d_in[8];
    const float* W_ih    = (const float*)d_in[9];
    const float* W_hh    = (const float*)d_in[10];
    const float* b_ih    = (const float*)d_in[11];
    const float* b_hh    = (const float*)d_in[12];
    const float* out_W   = (const float*)d_in[13];
    const float* out_b   = (const float*)d_in[14];

    float* out   = (float*)d_out;
    float* logp  = out;                 // [V]
    float* h_new = out + V;             // [H]
    float* c_new = out + V + H;         // [H]
    float* attnw = out + V + 2 * H;     // [L]

    k0_attn<<<1, 384>>>(input, h_hid, enc, emb, attn_W, attn_b, attnw);
    k1_comb_hh<<<640, 256>>>(h_hid, comb_W, comb_b, W_hh, b_ih, b_hh);
    k2_gates_cell<<<128, 256>>>(c_hid, W_ih, h_new, c_new);
    k3_out<<<TILES, 256>>>(out_W, out_b, logp);
    k_lse<<<1, 256>>>();
    k4_sub<<<(V + 255) / 256, 256>>>(logp);
}

// round 8
// speedup vs baseline: 1.1875x; 1.0705x over previous
#include <cuda_runtime.h>
#include <math_constants.h>

#define H 1024
#define V 50257
#define L 12
#define TILES ((V + 7) / 8)          // 6283 blocks in k3, 8 rows each

// ---- device scratch (no allocations allowed), 16B-aligned ----
__device__ __align__(16) float g_x[H];         // relu(combine) output
__device__ __align__(16) float g_h[H];         // h_new (aligned copy)
__device__ __align__(16) float g_gih[4 * H];   // W_ih@x
__device__ __align__(16) float g_hh[4 * H];    // W_hh@h0 + b_ih + b_hh
__device__ __align__(16) float g_ps[TILES];    // per-block sum(exp(logit))
__device__ float g_lse;                        // final log-sum-exp

__device__ __forceinline__ float warp_sum(float v) {
#pragma unroll
    for (int o = 16; o; o >>= 1) v += __shfl_xor_sync(0xffffffffu, v, o);
    return v;
}

__device__ __forceinline__ float4 ldcs4(const float4* p) { return __ldcs(p); }

// ============================================================
// Kernel 1: attention (redundant per block) + combine.
// 128 blocks x 256 threads. Inputs for the attention part are
// L2-resident after block 0 touches them; each block recomputes
// the 12 attention weights, then streams its 8 comb rows.
// ============================================================
__global__ void k1_attn_comb(const int* input,
                             const float* __restrict__ h_hidden,
                             const float* __restrict__ enc,
                             const float* __restrict__ emb,
                             const float* __restrict__ attn_W,
                             const float* __restrict__ attn_b,
                             const float* __restrict__ comb_W,
                             const float* __restrict__ comb_b,
                             float* __restrict__ attnw_out) {
    __shared__ __align__(16) float s_in[2 * H];   // [emb ; h0]
    __shared__ __align__(16) float s_cx[2 * H];   // [emb ; applied]
    __shared__ float s_logit[L];
    __shared__ float s_w[L];
    const int tid = threadIdx.x;
    const int w = tid >> 5, lane = tid & 31;

    const int idx = input[0];     // low 32 bits of LE int64 index
    const float* e = emb + (size_t)idx * H;
    for (int i = tid; i < H; i += 256) {
        float v = e[i];
        s_in[i] = v;
        s_cx[i] = v;
        s_in[H + i] = h_hidden[i];
    }
    __syncthreads();

    const float4* s_in4 = (const float4*)s_in;
    for (int l = w; l < L; l += 8) {
        const float4* row = (const float4*)(attn_W + (size_t)l * 2 * H);
        float acc = 0.f;
#pragma unroll
        for (int t = 0; t < 16; t++) {
            float4 a = row[lane + 32 * t];
            float4 b = s_in4[lane + 32 * t];
            acc += a.x * b.x + a.y * b.y + a.z * b.z + a.w * b.w;
        }
        acc = warp_sum(acc);
        if (lane == 0) s_logit[l] = acc + attn_b[l];
    }
    __syncthreads();

    if (tid == 0) {
        float m = -1e30f;
#pragma unroll
        for (int l = 0; l < L; l++) m = fmaxf(m, s_logit[l]);
        float s = 0.f;
#pragma unroll
        for (int l = 0; l < L; l++) { float ex = expf(s_logit[l] - m); s_w[l] = ex; s += ex; }
        float inv = 1.f / s;
#pragma unroll
        for (int l = 0; l < L; l++) s_w[l] *= inv;
        if (blockIdx.x == 0)
#pragma unroll
            for (int l = 0; l < L; l++) attnw_out[l] = s_w[l];
    }
    __syncthreads();

    for (int j = tid; j < H; j += 256) {
        float acc = 0.f;
#pragma unroll
        for (int l = 0; l < L; l++) acc += s_w[l] * enc[l * H + j];
        s_cx[H + j] = acc;
    }
    __syncthreads();

    const int r = blockIdx.x * 8 + w;
    const float4* s_cx4 = (const float4*)s_cx;
    const float4* row = (const float4*)(comb_W + (size_t)r * 2 * H);
    float acc = 0.f;
#pragma unroll
    for (int t = 0; t < 16; t++) {
        float4 a = ldcs4(row + lane + 32 * t);
        float4 b = s_cx4[lane + 32 * t];
        acc += a.x * b.x + a.y * b.y + a.z * b.z + a.w * b.w;
    }
    acc = warp_sum(acc);
    if (lane == 0) g_x[r] = fmaxf(acc + comb_b[r], 0.f);
}

// ============================================================
// Kernel 2: unified LSTM gate streamer, 1024 blocks x 256 threads.
//   blocks 0..511   : ih rows (8/block): g_gih[r] = W_ih[r]@x
//   blocks 512..1023: hh rows (8/block): g_hh[r]  = W_hh[r]@h0 + b_ih + b_hh
// Warp-per-row, low regs, high occupancy — 33.5 MB in one stream.
// ============================================================
__global__ void __launch_bounds__(256, 6)
k2_gates(const float* __restrict__ h_hidden,
         const float* __restrict__ W_ih,
         const float* __restrict__ W_hh,
         const float* __restrict__ b_ih,
         const float* __restrict__ b_hh) {
    __shared__ __align__(16) float4 s_v[256];
    const int tid = threadIdx.x;
    const int w = tid >> 5, lane = tid & 31;

    if (blockIdx.x < 512) {
        s_v[tid] = ((const float4*)g_x)[tid];
        __syncthreads();
        const int r = blockIdx.x * 8 + w;              // [0, 4096)
        const float4* row = (const float4*)(W_ih + (size_t)r * H);
        float acc = 0.f;
#pragma unroll
        for (int t = 0; t < 8; t++) {
            float4 a = ldcs4(row + lane + 32 * t);
            float4 b = s_v[lane + 32 * t];
            acc += a.x * b.x + a.y * b.y + a.z * b.z + a.w * b.w;
        }
        acc = warp_sum(acc);
        if (lane == 0) g_gih[r] = acc;
    } else {
        s_v[tid] = ((const float4*)h_hidden)[tid];
        __syncthreads();
        const int r = (blockIdx.x - 512) * 8 + w;      // [0, 4096)
        const float4* row = (const float4*)(W_hh + (size_t)r * H);
        float acc = 0.f;
#pragma unroll
        for (int t = 0; t < 8; t++) {
            float4 a = ldcs4(row + lane + 32 * t);
            float4 b = s_v[lane + 32 * t];
            acc += a.x * b.x + a.y * b.y + a.z * b.z + a.w * b.w;
        }
        acc = warp_sum(acc);
        if (lane == 0) g_hh[r] = acc + b_ih[r] + b_hh[r];
    }
}

// ============================================================
// Kernel 2b: LSTM cell elementwise. 4 blocks x 256 threads.
// ============================================================
__global__ void k2b_cell(const float* __restrict__ c_hidden,
                         float* __restrict__ h_new,
                         float* __restrict__ c_new) {
    const int j = blockIdx.x * 256 + threadIdx.x;
    float gi = g_gih[j]         + g_hh[j];
    float gf = g_gih[H + j]     + g_hh[H + j];
    float gg = g_gih[2 * H + j] + g_hh[2 * H + j];
    float go = g_gih[3 * H + j] + g_hh[3 * H + j];
    float si = 1.f / (1.f + expf(-gi));
    float sf = 1.f / (1.f + expf(-gf));
    float so = 1.f / (1.f + expf(-go));
    float c = sf * c_hidden[j] + si * tanhf(gg);
    float h = so * tanhf(c);
    c_new[j] = c;
    h_new[j] = h;
    g_h[j] = h;
}

// ============================================================
// Kernel 3: output projection (50257 x 1024), 8 rows/block,
// one warp per row; per-block sum(exp(logit)) partial.
// Clean epilogue — no fences/atomics. Bounded logits: plain exp.
// ============================================================
__global__ void k3_out(const float* __restrict__ out_W,
                       const float* __restrict__ out_b,
                       float* __restrict__ logits) {
    __shared__ __align__(16) float4 s_h[256];
    __shared__ float s_l[8];
    const int tid = threadIdx.x;
    s_h[tid] = ((const float4*)g_h)[tid];
    __syncthreads();

    const int w = tid >> 5, lane = tid & 31;
    const int r = blockIdx.x * 8 + w;
    float l = -CUDART_INF_F;
    if (r < V) {
        const float4* row = (const float4*)(out_W + (size_t)r * H);
        float acc = 0.f;
#pragma unroll
        for (int t = 0; t < 8; t++) {
            float4 a = ldcs4(row + lane + 32 * t);
            float4 b = s_h[lane + 32 * t];
            acc += a.x * b.x + a.y * b.y + a.z * b.z + a.w * b.w;
        }
        acc = warp_sum(acc);
        if (lane == 0) {
            l = acc + out_b[r];
            logits[r] = l;
        }
    }
    if (lane == 0) s_l[w] = l;
    __syncthreads();
    if (tid == 0) {
        float s = 0.f;
#pragma unroll
        for (int i = 0; i < 8; i++) {
            float v = s_l[i];
            if (v != -CUDART_INF_F) s += expf(v);
        }
        g_ps[blockIdx.x] = s;
    }
}

// ============================================================
// Kernel 3.5: reduce 6283 L2-resident partials -> g_lse.
// ============================================================
__global__ void k_lse() {
    __shared__ float s_part[8];
    const int tid = threadIdx.x;
    const int w = tid >> 5, lane = tid & 31;
    float s = 0.f;
    for (int i = tid; i < TILES; i += 256) s += g_ps[i];
    s = warp_sum(s);
    if (lane == 0) s_part[w] = s;
    __syncthreads();
    if (tid == 0) {
        float tot = 0.f;
#pragma unroll
        for (int i = 0; i < 8; i++) tot += s_part[i];
        g_lse = logf(tot);
    }
}

// ============================================================
// Kernel 4: logp[i] = logits[i] - g_lse (L2-resident elementwise)
// ============================================================
__global__ void k4_sub(float* __restrict__ logp) {
    const int i = blockIdx.x * 256 + threadIdx.x;
    if (i < V) logp[i] -= g_lse;
}

// ============================================================
extern "C" void kernel_launch(void* const* d_in, const int* in_sizes, int n_in,
                              void* d_out, int out_size) {
    const int*   input   = (const int*)  d_in[0];
    const float* h_hid   = (const float*)d_in[1];
    const float* c_hid   = (const float*)d_in[2];
    const float* enc     = (const float*)d_in[3];
    const float* emb     = (const float*)d_in[4];
    const float* attn_W  = (const float*)d_in[5];
    const float* attn_b  = (const float*)d_in[6];
    const float* comb_W  = (const float*)d_in[7];
    const float* comb_b  = (const float*)d_in[8];
    const float* W_ih    = (const float*)d_in[9];
    const float* W_hh    = (const float*)d_in[10];
    const float* b_ih    = (const float*)d_in[11];
    const float* b_hh    = (const float*)d_in[12];
    const float* out_W   = (const float*)d_in[13];
    const float* out_b   = (const float*)d_in[14];

    float* out   = (float*)d_out;
    float* logp  = out;                 // [V]
    float* h_new = out + V;             // [H]
    float* c_new = out + V + H;         // [H]
    float* attnw = out + V + 2 * H;     // [L]

    k1_attn_comb<<<128, 256>>>(input, h_hid, enc, emb, attn_W, attn_b,
                               comb_W, comb_b, attnw);
    k2_gates<<<1024, 256>>>(h_hid, W_ih, W_hh, b_ih, b_hh);
    k2b_cell<<<4, 256>>>(c_hid, h_new, c_new);
    k3_out<<<TILES, 256>>>(out_W, out_b, logp);
    k_lse<<<1, 256>>>();
    k4_sub<<<(V + 255) / 256, 256>>>(logp);
}